// round 1
// baseline (speedup 1.0000x reference)
#include <cuda_runtime.h>
#include <math.h>

// Problem constants
#define NROW 4096     // N = B*V
#define BATCH 2048
#define EDIM 256
#define NH   4
#define FS   64
#define INV_T (1.0f/0.07f)

// Scratch (no allocation allowed in kernel_launch)
__device__ float    g_fnorm[NROW * EDIM];      // normalized features, row-major [i][e]
__device__ unsigned g_bits[BATCH];             // packed label bitmasks
__device__ float    g_part[2][NROW][10];       // per-row partials per j-chunk:
                                               // [0..3]=s[h], [4]=A, [5..8]=C[h], [9]=den

// ---------------------------------------------------------------------------
// Pack label rows (10 binary floats) into bitmasks.
// mask(b,b') = (labels[b] . labels[b'] > 0)  <=>  (bits[b] & bits[b']) != 0
// ---------------------------------------------------------------------------
__global__ void k_bits(const float* __restrict__ labels) {
    int b = blockIdx.x * 256 + threadIdx.x;
    if (b < BATCH) {
        unsigned m = 0;
        #pragma unroll
        for (int c = 0; c < 10; ++c)
            if (labels[b * 10 + c] > 0.5f) m |= (1u << c);
        g_bits[b] = m;
    }
}

// ---------------------------------------------------------------------------
// Normalize per (row, head). Stacked row i = v*BATCH + b (view-major stacking).
// features layout (B, V, E): index = b*512 + v*256 + e
// ---------------------------------------------------------------------------
__global__ void k_norm(const float* __restrict__ feats) {
    int i = blockIdx.x;
    int e = threadIdx.x;
    int v = i >> 11;
    int b = i & (BATCH - 1);
    float val = feats[b * 512 + v * 256 + e];
    __shared__ float sq[EDIM];
    __shared__ float rn[NH];
    sq[e] = val * val;
    __syncthreads();
    if (e < NH) {
        float s = 0.f;
        #pragma unroll
        for (int t = 0; t < FS; ++t) s += sq[e * FS + t];
        rn[e] = 1.0f / fmaxf(sqrtf(s), 1e-12f);
    }
    __syncthreads();
    g_fnorm[i * EDIM + e] = val * rn[e >> 6];
}

// ---------------------------------------------------------------------------
// Main fused kernel.
// Grid: (2 j-chunks, 64 i-tiles). Block: 256 threads (16 tx x 16 ty).
// Each CTA owns 64 i-rows, streams j over its 2048-wide chunk in 64-tiles.
// Micro-tile per thread: 4 i x 4 j x 4 heads (64 fp32 accumulators).
//
// Shared tiles stored TRANSPOSED: s[e][j-local], as float4 slots of 4
// consecutive j (or i), with XOR swizzle slot' = slot ^ ((e>>2)&15) so that
// both the transposing stores and the compute LDS.128 are (near) conflict-free.
// ---------------------------------------------------------------------------
__global__ __launch_bounds__(256, 1) void k_main() {
    extern __shared__ unsigned char smem_raw[];
    float*    sAf   = (float*)smem_raw;                  // 256*64 floats (64KB)
    float*    sBf   = sAf + EDIM * 64;                   // 256*64 floats (64KB)
    unsigned* sbits = (unsigned*)(sBf + EDIM * 64);      // 2048 u32 (8KB)
    const float4* sA4 = (const float4*)sAf;
    const float4* sB4 = (const float4*)sBf;

    const int tid = threadIdx.x;
    const int tx = tid & 15, ty = tid >> 4;
    const int i0 = blockIdx.y * 64;
    const int jbase = blockIdx.x * 2048;

    // Load label bits to shared
    for (int idx = tid; idx < BATCH; idx += 256) sbits[idx] = g_bits[idx];

    // Load + transpose + swizzle the A (anchor) tile once per CTA
    for (int idx = tid; idx < 64 * 64; idx += 256) {
        int r = idx >> 6, c = idx & 63;       // r = local i row, c = float4 col along e
        float4 vv = *(const float4*)&g_fnorm[(i0 + r) * EDIM + c * 4];
        int sw4 = (((r >> 2) ^ (c & 15)) << 2) + (r & 3);  // swizzled float offset in row
        sAf[(4 * c + 0) * 64 + sw4] = vv.x;
        sAf[(4 * c + 1) * 64 + sw4] = vv.y;
        sAf[(4 * c + 2) * 64 + sw4] = vv.z;
        sAf[(4 * c + 3) * 64 + sw4] = vv.w;
    }

    // Per-row accumulators (4 local i rows per thread)
    float s_acc[4][4], A_acc[4], C_acc[4][4], den_acc[4];
    #pragma unroll
    for (int ii = 0; ii < 4; ++ii) {
        A_acc[ii] = 0.f; den_acc[ii] = 0.f;
        #pragma unroll
        for (int h = 0; h < 4; ++h) { s_acc[ii][h] = 0.f; C_acc[ii][h] = 0.f; }
    }

    __syncthreads();   // sbits + sA ready

    int ig[4]; unsigned ibits[4];
    #pragma unroll
    for (int ii = 0; ii < 4; ++ii) {
        ig[ii] = i0 + ty * 4 + ii;
        ibits[ii] = sbits[ig[ii] & (BATCH - 1)];
    }

    for (int jt = 0; jt < 32; ++jt) {
        const int j0 = jbase + jt * 64;
        __syncthreads();  // previous tile's compute done before overwrite
        for (int idx = tid; idx < 64 * 64; idx += 256) {
            int r = idx >> 6, c = idx & 63;
            float4 vv = *(const float4*)&g_fnorm[(j0 + r) * EDIM + c * 4];
            int sw4 = (((r >> 2) ^ (c & 15)) << 2) + (r & 3);
            sBf[(4 * c + 0) * 64 + sw4] = vv.x;
            sBf[(4 * c + 1) * 64 + sw4] = vv.y;
            sBf[(4 * c + 2) * 64 + sw4] = vv.z;
            sBf[(4 * c + 3) * 64 + sw4] = vv.w;
        }
        __syncthreads();

        // ---- GEMM micro-kernel: acc[h][ii][jj] ----
        float acc[4][4][4];
        #pragma unroll
        for (int h = 0; h < 4; ++h)
            #pragma unroll
            for (int ii = 0; ii < 4; ++ii)
                #pragma unroll
                for (int jj = 0; jj < 4; ++jj) acc[h][ii][jj] = 0.f;

        #pragma unroll
        for (int h = 0; h < 4; ++h) {
            #pragma unroll 8
            for (int kk = 0; kk < 64; ++kk) {
                int k = h * 64 + kk;
                int swz = (k >> 2) & 15;
                float4 a4 = sA4[k * 16 + (ty ^ swz)];
                float4 b4 = sB4[k * 16 + (tx ^ swz)];
                float av[4] = {a4.x, a4.y, a4.z, a4.w};
                float bv[4] = {b4.x, b4.y, b4.z, b4.w};
                #pragma unroll
                for (int ii = 0; ii < 4; ++ii)
                    #pragma unroll
                    for (int jj = 0; jj < 4; ++jj)
                        acc[h][ii][jj] = fmaf(av[ii], bv[jj], acc[h][ii][jj]);
            }
        }

        // ---- Epilogue: argmax head, exp-sums, mask accumulation ----
        int jg[4]; unsigned jbits[4];
        #pragma unroll
        for (int jj = 0; jj < 4; ++jj) {
            jg[jj] = j0 + tx * 4 + jj;
            jbits[jj] = sbits[jg[jj] & (BATCH - 1)];
        }

        #pragma unroll
        for (int ii = 0; ii < 4; ++ii) {
            #pragma unroll
            for (int jj = 0; jj < 4; ++jj) {
                float d0 = acc[0][ii][jj], d1 = acc[1][ii][jj];
                float d2 = acc[2][ii][jj], d3 = acc[3][ii][jj];
                // first-max argmax (matches jnp.argmax tie-break)
                float best = d0; int hb = 0;
                if (d1 > best) { best = d1; hb = 1; }
                if (d2 > best) { best = d2; hb = 2; }
                if (d3 > best) { best = d3; hb = 3; }
                bool diag = (jg[jj] == ig[ii]);
                float e0 = __expf((d0 - 1.f) * INV_T);
                float e1 = __expf((d1 - 1.f) * INV_T);
                float e2 = __expf((d2 - 1.f) * INV_T);
                float e3 = __expf((d3 - 1.f) * INV_T);
                if (!diag) {
                    s_acc[ii][0] += e0; s_acc[ii][1] += e1;
                    s_acc[ii][2] += e2; s_acc[ii][3] += e3;
                }
                float mv = (!diag && ((ibits[ii] & jbits[jj]) != 0u)) ? 1.0f : 0.0f;
                A_acc[ii]  += mv * best * INV_T;
                den_acc[ii] += mv;
                C_acc[ii][0] += (hb == 0) ? mv : 0.f;
                C_acc[ii][1] += (hb == 1) ? mv : 0.f;
                C_acc[ii][2] += (hb == 2) ? mv : 0.f;
                C_acc[ii][3] += (hb == 3) ? mv : 0.f;
            }
        }
    }

    // ---- Reduce across the 16 tx lanes (same i rows), pure sums ----
    #pragma unroll
    for (int off = 8; off > 0; off >>= 1) {
        #pragma unroll
        for (int ii = 0; ii < 4; ++ii) {
            #pragma unroll
            for (int h = 0; h < 4; ++h) {
                s_acc[ii][h] += __shfl_xor_sync(0xffffffffu, s_acc[ii][h], off);
                C_acc[ii][h] += __shfl_xor_sync(0xffffffffu, C_acc[ii][h], off);
            }
            A_acc[ii]   += __shfl_xor_sync(0xffffffffu, A_acc[ii], off);
            den_acc[ii] += __shfl_xor_sync(0xffffffffu, den_acc[ii], off);
        }
    }
    if (tx == 0) {
        #pragma unroll
        for (int ii = 0; ii < 4; ++ii) {
            float* p = g_part[blockIdx.x][ig[ii]];
            p[0] = s_acc[ii][0]; p[1] = s_acc[ii][1];
            p[2] = s_acc[ii][2]; p[3] = s_acc[ii][3];
            p[4] = A_acc[ii];
            p[5] = C_acc[ii][0]; p[6] = C_acc[ii][1];
            p[7] = C_acc[ii][2]; p[8] = C_acc[ii][3];
            p[9] = den_acc[ii];
        }
    }
}

// ---------------------------------------------------------------------------
// Finalize: merge j-chunk partials, per-row loss, finite-filtered mean.
// Deterministic fixed-order tree reduction, single CTA.
// ---------------------------------------------------------------------------
__global__ void k_final(float* __restrict__ out) {
    int tid = threadIdx.x;
    __shared__ float ssum[512];
    __shared__ float scnt[512];
    float lsum = 0.f, lcnt = 0.f;
    for (int i = tid; i < NROW; i += 512) {
        float A   = g_part[0][i][4] + g_part[1][i][4];
        float den = g_part[0][i][9] + g_part[1][i][9];
        float sub = 0.f;
        #pragma unroll
        for (int h = 0; h < 4; ++h) {
            float sv = g_part[0][i][h]     + g_part[1][i][h];
            float Cv = g_part[0][i][5 + h] + g_part[1][i][5 + h];
            sub += Cv * (INV_T + logf(sv));
        }
        // loss = -(T/baseT) * (A - sub)/den ; T/baseT = 1
        float loss = -(A - sub) / den;
        if (isfinite(loss)) { lsum += loss; lcnt += 1.f; }
    }
    ssum[tid] = lsum; scnt[tid] = lcnt;
    __syncthreads();
    for (int st = 256; st > 0; st >>= 1) {
        if (tid < st) { ssum[tid] += ssum[tid + st]; scnt[tid] += scnt[tid + st]; }
        __syncthreads();
    }
    if (tid == 0) out[0] = ssum[0] / scnt[0];
}

// ---------------------------------------------------------------------------
extern "C" void kernel_launch(void* const* d_in, const int* in_sizes, int n_in,
                              void* d_out, int out_size) {
    const float* feats  = (const float*)d_in[0];   // (2048, 2, 256) fp32
    const float* labels = (const float*)d_in[1];   // (2048, 10) fp32
    (void)in_sizes; (void)n_in; (void)out_size;

    k_bits<<<(BATCH + 255) / 256, 256>>>(labels);
    k_norm<<<NROW, 256>>>(feats);

    size_t shmem = (size_t)EDIM * 64 * sizeof(float) * 2 + BATCH * sizeof(unsigned); // 139264
    cudaFuncSetAttribute(k_main, cudaFuncAttributeMaxDynamicSharedMemorySize, (int)shmem);
    dim3 grid(2, 64);
    k_main<<<grid, 256, shmem>>>();

    k_final<<<1, 512>>>((float*)d_out);
}

// round 3
// speedup vs baseline: 4.4544x; 4.4544x over previous
#include <cuda_runtime.h>
#include <cuda_fp16.h>
#include <cstdint>
#include <math.h>

#define NROW 4096
#define BATCH 2048
#define INV_T 14.285714285714286f
#define K2C   20.609929155556625f   /* INV_T * log2(e) */

__device__ __half   g_fh[NROW * 256];     // normalized features, fp16, [i][e]
__device__ unsigned g_bits[BATCH];
__device__ float    g_part[4][NROW][10];  // [0..3]=s[h], [4]=A(dot units), [5..8]=C[h], [9]=den
__device__ float    g_red[32];

// ---------------------------------------------------------------------------
__device__ __forceinline__ uint32_t smem_u32(const void* p) {
    uint32_t a;
    asm("{ .reg .u64 t; cvta.to.shared.u64 t, %1; cvt.u32.u64 %0, t; }" : "=r"(a) : "l"(p));
    return a;
}
__device__ __forceinline__ float fexp2(float x) {
    float y; asm("ex2.approx.f32 %0, %1;" : "=f"(y) : "f"(x)); return y;
}

#define CP_ASYNC(dst, src) asm volatile("cp.async.cg.shared.global [%0], [%1], 16;" :: "r"(dst), "l"(src) : "memory")
#define CP_COMMIT()        asm volatile("cp.async.commit_group;" ::: "memory")
#define CP_WAIT0()         asm volatile("cp.async.wait_group 0;" ::: "memory")

#define LDM4(R, addr) asm volatile( \
    "ldmatrix.sync.aligned.m8n8.x4.shared.b16 {%0,%1,%2,%3}, [%4];" \
    : "=r"((R)[0]), "=r"((R)[1]), "=r"((R)[2]), "=r"((R)[3]) : "r"(addr))

#define MMA16816(C, A, b0, b1) asm volatile( \
    "mma.sync.aligned.m16n8k16.row.col.f32.f16.f16.f32 " \
    "{%0,%1,%2,%3}, {%4,%5,%6,%7}, {%8,%9}, {%0,%1,%2,%3};" \
    : "+f"((C)[0]), "+f"((C)[1]), "+f"((C)[2]), "+f"((C)[3]) \
    : "r"((A)[0]), "r"((A)[1]), "r"((A)[2]), "r"((A)[3]), "r"(b0), "r"(b1))

// ---------------------------------------------------------------------------
__global__ void k_bits(const float* __restrict__ labels) {
    int b = blockIdx.x * 256 + threadIdx.x;
    if (b < BATCH) {
        unsigned m = 0;
        #pragma unroll
        for (int c = 0; c < 10; ++c)
            if (labels[b * 10 + c] > 0.5f) m |= (1u << c);
        g_bits[b] = m;
    }
}

// Normalize per (row, head); stacked row i = v*BATCH + b; store fp16.
__global__ void k_norm(const float* __restrict__ feats) {
    int i = blockIdx.x, e = threadIdx.x;
    int v = i >> 11, b = i & (BATCH - 1);
    float val = feats[b * 512 + v * 256 + e];
    __shared__ float sq[256];
    __shared__ float rn[4];
    sq[e] = val * val;
    __syncthreads();
    if (e < 4) {
        float s = 0.f;
        #pragma unroll
        for (int t = 0; t < 64; ++t) s += sq[e * 64 + t];
        rn[e] = 1.0f / fmaxf(sqrtf(s), 1e-12f);
    }
    __syncthreads();
    g_fh[i * 256 + e] = __float2half_rn(val * rn[e >> 6]);
}

// ---------------------------------------------------------------------------
// B-tile prefetch: 64 rows x 4 heads x 64 fp16. Head blocks of 8KB,
// 128B rows, 16B-chunk swizzle: chunk' = chunk ^ (row & 7).
// ---------------------------------------------------------------------------
__device__ __forceinline__ void prefetch_B(uint32_t Bb, const __half* gB, int tid) {
    #pragma unroll
    for (int q = 0; q < 8; ++q) {
        int idx = q * 256 + tid;
        int r = idx >> 5, cc = idx & 31;
        int h = cc >> 3, c = cc & 7;
        uint32_t dst = Bb + h * 8192 + r * 128 + ((c ^ (r & 7)) << 4);
        const void* src = gB + r * 256 + h * 64 + c * 8;
        CP_ASYNC(dst, src);
    }
}

// ---------------------------------------------------------------------------
// Main: fp16 mma.sync GEMM + fused epilogue.
// Grid (4 j-chunks, 32 i-tiles), 256 threads = 8 warps (4 i x 2 j).
// SMEM: A 64KB | B0 32KB | B1 32KB | bits 8KB | red 5KB.
// ---------------------------------------------------------------------------
__global__ __launch_bounds__(256, 1) void k_main() {
    extern __shared__ unsigned char smraw[];
    uint32_t raw  = smem_u32(smraw);
    uint32_t base = (raw + 127) & ~127u;
    unsigned char* sm = smraw + (base - raw);

    const uint32_t Ab  = base;
    const uint32_t B0b = base + 65536;
    const uint32_t B1b = base + 98304;
    unsigned* sbits = (unsigned*)(sm + 131072);
    float*    red   = (float*)(sm + 139264);

    const int tid = threadIdx.x;
    const int lane = tid & 31, wid = tid >> 5;
    const int wi = wid >> 1, wj = wid & 1;
    const int i0 = blockIdx.y * 128;
    const int jc = blockIdx.x, jbase = jc * 1024;

    // label bits
    for (int idx = tid; idx < BATCH; idx += 256) sbits[idx] = g_bits[idx];

    // A tile: 128 rows x 32 chunks (head blocks of 16KB)
    {
        const __half* gA = g_fh + (size_t)i0 * 256;
        #pragma unroll
        for (int q = 0; q < 16; ++q) {
            int idx = q * 256 + tid;
            int r = idx >> 5, cc = idx & 31;
            int h = cc >> 3, c = cc & 7;
            uint32_t dst = Ab + h * 16384 + r * 128 + ((c ^ (r & 7)) << 4);
            const void* src = gA + r * 256 + h * 64 + c * 8;
            CP_ASYNC(dst, src);
        }
    }
    prefetch_B(B0b, g_fh + (size_t)jbase * 256, tid);
    CP_COMMIT();

    // per-thread ldmatrix geometry (all swizzles reduce to lane&7)
    const int l7 = lane & 7;
    const int mrow0 = wi * 32 + ((lane & 8) ? 8 : 0) + l7;
    const int khA = (lane >> 4) & 1;
    const uint32_t aoff0 = (uint32_t)(mrow0 * 128);
    const uint32_t aoff1 = aoff0 + 16 * 128;
    const int nrow = (((lane >> 4) & 1) << 3) + l7;
    const int khB = (lane >> 3) & 1;
    const uint32_t boff0 = (uint32_t)((wj * 32 + nrow) * 128);
    const uint32_t boff1 = boff0 + 16 * 128;

    // anchor rows owned by this thread (4 of them)
    int ig[4]; unsigned ibit[4];
    #pragma unroll
    for (int ri = 0; ri < 4; ++ri) {
        int ms = ri >> 1, fh = ri & 1;
        ig[ri] = i0 + wi * 32 + ms * 16 + fh * 8 + (lane >> 2);
    }

    float s[4][4], Cc[4][4], Aa[4], dn[4];
    #pragma unroll
    for (int ri = 0; ri < 4; ++ri) {
        Aa[ri] = 0.f; dn[ri] = 0.f;
        #pragma unroll
        for (int h = 0; h < 4; ++h) { s[ri][h] = 0.f; Cc[ri][h] = 0.f; }
    }

    for (int jt = 0; jt < 16; ++jt) {
        const uint32_t Bb = (jt & 1) ? B1b : B0b;
        const int j0 = jbase + jt * 64;

        CP_WAIT0();
        __syncthreads();   // buffer ready; prev compute done

        if (jt + 1 < 16)
            prefetch_B((jt & 1) ? B0b : B1b, g_fh + (size_t)(j0 + 64) * 256, tid);
        CP_COMMIT();

        if (jt == 0) {
            #pragma unroll
            for (int ri = 0; ri < 4; ++ri) ibit[ri] = sbits[ig[ri] & (BATCH - 1)];
        }

        // ---- MMA: acc[h][ms][ns][frag] ----
        float acc[4][2][4][4];
        #pragma unroll
        for (int h = 0; h < 4; ++h)
            #pragma unroll
            for (int ms = 0; ms < 2; ++ms)
                #pragma unroll
                for (int ns = 0; ns < 4; ++ns)
                    #pragma unroll
                    for (int f = 0; f < 4; ++f) acc[h][ms][ns][f] = 0.f;

        #pragma unroll
        for (int h = 0; h < 4; ++h) {
            const uint32_t Ah = Ab + h * 16384;
            const uint32_t Bh = Bb + h * 8192;
            #pragma unroll
            for (int ks = 0; ks < 4; ++ks) {
                uint32_t A0[4], A1[4], Bq0[4], Bq1[4];
                uint32_t swA = (uint32_t)(((ks * 2 + khA) ^ l7) << 4);
                uint32_t swB = (uint32_t)(((ks * 2 + khB) ^ l7) << 4);
                LDM4(A0, Ah + aoff0 + swA);
                LDM4(A1, Ah + aoff1 + swA);
                LDM4(Bq0, Bh + boff0 + swB);
                LDM4(Bq1, Bh + boff1 + swB);
                MMA16816(acc[h][0][0], A0, Bq0[0], Bq0[1]);
                MMA16816(acc[h][0][1], A0, Bq0[2], Bq0[3]);
                MMA16816(acc[h][0][2], A0, Bq1[0], Bq1[1]);
                MMA16816(acc[h][0][3], A0, Bq1[2], Bq1[3]);
                MMA16816(acc[h][1][0], A1, Bq0[0], Bq0[1]);
                MMA16816(acc[h][1][1], A1, Bq0[2], Bq0[3]);
                MMA16816(acc[h][1][2], A1, Bq1[0], Bq1[1]);
                MMA16816(acc[h][1][3], A1, Bq1[2], Bq1[3]);
            }
        }

        // ---- Epilogue (thread-local) ----
        int jg[8]; unsigned jb[8];
        #pragma unroll
        for (int ns = 0; ns < 4; ++ns)
            #pragma unroll
            for (int cp = 0; cp < 2; ++cp) {
                int q = ns * 2 + cp;
                jg[q] = j0 + wj * 32 + ns * 8 + 2 * (lane & 3) + cp;
                jb[q] = sbits[jg[q] & (BATCH - 1)];
            }

        #pragma unroll
        for (int ms = 0; ms < 2; ++ms)
            #pragma unroll
            for (int fh = 0; fh < 2; ++fh) {
                const int ri = ms * 2 + fh;
                #pragma unroll
                for (int ns = 0; ns < 4; ++ns)
                    #pragma unroll
                    for (int cp = 0; cp < 2; ++cp) {
                        const int q = ns * 2 + cp;
                        const int f = fh * 2 + cp;
                        float d0 = acc[0][ms][ns][f];
                        float d1 = acc[1][ms][ns][f];
                        float d2 = acc[2][ms][ns][f];
                        float d3 = acc[3][ms][ns][f];
                        float best = d0; int hb = 0;
                        if (d1 > best) { best = d1; hb = 1; }
                        if (d2 > best) { best = d2; hb = 2; }
                        if (d3 > best) { best = d3; hb = 3; }
                        float nd = (jg[q] == ig[ri]) ? 0.f : 1.f;
                        float e0 = fexp2(fmaf(d0, K2C, -K2C));
                        float e1 = fexp2(fmaf(d1, K2C, -K2C));
                        float e2 = fexp2(fmaf(d2, K2C, -K2C));
                        float e3 = fexp2(fmaf(d3, K2C, -K2C));
                        s[ri][0] = fmaf(nd, e0, s[ri][0]);
                        s[ri][1] = fmaf(nd, e1, s[ri][1]);
                        s[ri][2] = fmaf(nd, e2, s[ri][2]);
                        s[ri][3] = fmaf(nd, e3, s[ri][3]);
                        float mv = ((ibit[ri] & jb[q]) != 0u) ? nd : 0.f;
                        Aa[ri] = fmaf(mv, best, Aa[ri]);
                        dn[ri] += mv;
                        Cc[ri][0] += (hb == 0) ? mv : 0.f;
                        Cc[ri][1] += (hb == 1) ? mv : 0.f;
                        Cc[ri][2] += (hb == 2) ? mv : 0.f;
                        Cc[ri][3] += (hb == 3) ? mv : 0.f;
                    }
            }
    }

    // ---- Reduce across the 4 lanes sharing rows (l&3 group) ----
    #pragma unroll
    for (int off = 1; off <= 2; off <<= 1) {
        #pragma unroll
        for (int ri = 0; ri < 4; ++ri) {
            #pragma unroll
            for (int h = 0; h < 4; ++h) {
                s[ri][h]  += __shfl_xor_sync(0xffffffffu, s[ri][h], off);
                Cc[ri][h] += __shfl_xor_sync(0xffffffffu, Cc[ri][h], off);
            }
            Aa[ri] += __shfl_xor_sync(0xffffffffu, Aa[ri], off);
            dn[ri] += __shfl_xor_sync(0xffffffffu, dn[ri], off);
        }
    }

    // ---- Combine the two j-half warps via smem; write partials ----
    if (wj == 0 && (lane & 3) == 0) {
        #pragma unroll
        for (int ri = 0; ri < 4; ++ri) {
            int lrow = wi * 32 + (ri >> 1) * 16 + (ri & 1) * 8 + (lane >> 2);
            float* p = &red[lrow * 10];
            p[0] = s[ri][0]; p[1] = s[ri][1]; p[2] = s[ri][2]; p[3] = s[ri][3];
            p[4] = Aa[ri];
            p[5] = Cc[ri][0]; p[6] = Cc[ri][1]; p[7] = Cc[ri][2]; p[8] = Cc[ri][3];
            p[9] = dn[ri];
        }
    }
    __syncthreads();
    if (wj == 1 && (lane & 3) == 0) {
        #pragma unroll
        for (int ri = 0; ri < 4; ++ri) {
            int lrow = wi * 32 + (ri >> 1) * 16 + (ri & 1) * 8 + (lane >> 2);
            float* p = &red[lrow * 10];
            float* o = g_part[jc][i0 + lrow];
            o[0] = p[0] + s[ri][0]; o[1] = p[1] + s[ri][1];
            o[2] = p[2] + s[ri][2]; o[3] = p[3] + s[ri][3];
            o[4] = p[4] + Aa[ri];
            o[5] = p[5] + Cc[ri][0]; o[6] = p[6] + Cc[ri][1];
            o[7] = p[7] + Cc[ri][2]; o[8] = p[8] + Cc[ri][3];
            o[9] = p[9] + dn[ri];
        }
    }
}

// ---------------------------------------------------------------------------
__global__ void k_loss() {
    int i = blockIdx.x * 256 + threadIdx.x;
    float s[4] = {0, 0, 0, 0}, C[4] = {0, 0, 0, 0}, A = 0.f, dnm = 0.f;
    #pragma unroll
    for (int c = 0; c < 4; ++c) {
        const float* p = g_part[c][i];
        #pragma unroll
        for (int h = 0; h < 4; ++h) { s[h] += p[h]; C[h] += p[5 + h]; }
        A += p[4]; dnm += p[9];
    }
    float sub = 0.f;
    #pragma unroll
    for (int h = 0; h < 4; ++h) sub += C[h] * (INV_T + logf(s[h]));
    float loss = -(A * INV_T - sub) / dnm;
    float ok = isfinite(loss) ? 1.f : 0.f;
    float ls = isfinite(loss) ? loss : 0.f;

    __shared__ float bs[256], bc[256];
    int t = threadIdx.x;
    bs[t] = ls; bc[t] = ok;
    __syncthreads();
    for (int st = 128; st > 0; st >>= 1) {
        if (t < st) { bs[t] += bs[t + st]; bc[t] += bc[t + st]; }
        __syncthreads();
    }
    if (t == 0) { g_red[blockIdx.x * 2] = bs[0]; g_red[blockIdx.x * 2 + 1] = bc[0]; }
}

__global__ void k_final(float* __restrict__ out) {
    if (threadIdx.x == 0) {
        float sv = 0.f, cv = 0.f;
        #pragma unroll
        for (int k = 0; k < 16; ++k) { sv += g_red[2 * k]; cv += g_red[2 * k + 1]; }
        out[0] = sv / cv;
    }
}

// ---------------------------------------------------------------------------
extern "C" void kernel_launch(void* const* d_in, const int* in_sizes, int n_in,
                              void* d_out, int out_size) {
    const float* feats  = (const float*)d_in[0];   // (2048, 2, 256) fp32
    const float* labels = (const float*)d_in[1];   // (2048, 10) fp32
    (void)in_sizes; (void)n_in; (void)out_size;

    k_bits<<<8, 256>>>(labels);
    k_norm<<<NROW, 256>>>(feats);

    const int shmem = 144384 + 128;
    cudaFuncSetAttribute(k_main, cudaFuncAttributeMaxDynamicSharedMemorySize, shmem);
    dim3 grid(4, 32);
    k_main<<<grid, 256, shmem>>>();

    k_loss<<<16, 256>>>();
    k_final<<<1, 32>>>((float*)d_out);
}

// round 4
// speedup vs baseline: 4.7166x; 1.0588x over previous
#include <cuda_runtime.h>
#include <cuda_fp16.h>
#include <cstdint>
#include <math.h>

#define NROW 4096
#define BATCH 2048
#define INV_T 14.285714285714286f
#define K2C   20.609929155556625f   /* INV_T * log2(e) */

__device__ __half   g_fh[NROW * 256];     // normalized features, fp16, [i][e]
__device__ unsigned g_bits[BATCH];
__device__ float    g_part[4][NROW][10];  // [0..3]=s[h], [4]=A(dot units), [5..8]=C[h], [9]=den
__device__ float    g_red[64];

// ---------------------------------------------------------------------------
__device__ __forceinline__ uint32_t smem_u32(const void* p) {
    uint32_t a;
    asm("{ .reg .u64 t; cvta.to.shared.u64 t, %1; cvt.u32.u64 %0, t; }" : "=r"(a) : "l"(p));
    return a;
}
__device__ __forceinline__ float fexp2(float x) {
    float y; asm("ex2.approx.f32 %0, %1;" : "=f"(y) : "f"(x)); return y;
}

#define CP_ASYNC(dst, src) asm volatile("cp.async.cg.shared.global [%0], [%1], 16;" :: "r"(dst), "l"(src) : "memory")
#define CP_COMMIT()        asm volatile("cp.async.commit_group;" ::: "memory")
#define CP_WAIT0()         asm volatile("cp.async.wait_group 0;" ::: "memory")

#define LDM4(R, addr) asm volatile( \
    "ldmatrix.sync.aligned.m8n8.x4.shared.b16 {%0,%1,%2,%3}, [%4];" \
    : "=r"((R)[0]), "=r"((R)[1]), "=r"((R)[2]), "=r"((R)[3]) : "r"(addr))

#define MMA16816(C, A, b0, b1) asm volatile( \
    "mma.sync.aligned.m16n8k16.row.col.f32.f16.f16.f32 " \
    "{%0,%1,%2,%3}, {%4,%5,%6,%7}, {%8,%9}, {%0,%1,%2,%3};" \
    : "+f"((C)[0]), "+f"((C)[1]), "+f"((C)[2]), "+f"((C)[3]) \
    : "r"((A)[0]), "r"((A)[1]), "r"((A)[2]), "r"((A)[3]), "r"(b0), "r"(b1))

// ---------------------------------------------------------------------------
__global__ void k_bits(const float* __restrict__ labels) {
    int b = blockIdx.x * 256 + threadIdx.x;
    if (b < BATCH) {
        unsigned m = 0;
        #pragma unroll
        for (int c = 0; c < 10; ++c)
            if (labels[b * 10 + c] > 0.5f) m |= (1u << c);
        g_bits[b] = m;
    }
}

// Normalize per (row, head); stacked row i = v*BATCH + b; store fp16.
__global__ void k_norm(const float* __restrict__ feats) {
    int i = blockIdx.x, e = threadIdx.x;
    int v = i >> 11, b = i & (BATCH - 1);
    float val = feats[b * 512 + v * 256 + e];
    float sq = val * val;
    #pragma unroll
    for (int off = 16; off > 0; off >>= 1)
        sq += __shfl_xor_sync(0xffffffffu, sq, off);
    __shared__ float ws[8];
    if ((e & 31) == 0) ws[e >> 5] = sq;
    __syncthreads();
    int h = e >> 6;
    float sum = ws[2 * h] + ws[2 * h + 1];
    float r = 1.0f / fmaxf(sqrtf(sum), 1e-12f);
    g_fh[i * 256 + e] = __float2half_rn(val * r);
}

// ---------------------------------------------------------------------------
// Tile loader: 64 rows x 4 heads x 64 fp16 (head blocks of 8KB, 128B rows,
// 16B-chunk swizzle chunk' = chunk ^ (row & 7)). 8 cp.async per thread.
// ---------------------------------------------------------------------------
__device__ __forceinline__ void prefetch_T(uint32_t Tb, const __half* gT, int tid) {
    #pragma unroll
    for (int q = 0; q < 8; ++q) {
        int idx = q * 256 + tid;
        int r = idx >> 5, cc = idx & 31;
        int h = cc >> 3, c = cc & 7;
        uint32_t dst = Tb + h * 8192 + r * 128 + ((c ^ (r & 7)) << 4);
        const void* src = gT + r * 256 + h * 64 + c * 8;
        CP_ASYNC(dst, src);
    }
}

// ---------------------------------------------------------------------------
// Per-tile epilogue. acc[h][ms][ns][f]. DIAG: this j-tile may contain i==j.
// ---------------------------------------------------------------------------
template<bool DIAG>
__device__ __forceinline__ void epi(
    const float (&acc)[4][2][2][4], int j0, int wj, int lane,
    const int (&ig)[4], const unsigned (&ibit)[4],
    float (&s)[4][4], float (&Aap)[4], unsigned (&Clo)[4], unsigned (&Chi)[4])
{
    const int cbase = j0 + wj * 16 + 2 * (lane & 3);
    uint2 bA = __ldg((const uint2*)&g_bits[cbase & (BATCH - 1)]);
    uint2 bB = __ldg((const uint2*)&g_bits[(cbase + 8) & (BATCH - 1)]);
    const unsigned jb[2][2] = {{bA.x, bA.y}, {bB.x, bB.y}};

    #pragma unroll
    for (int ms = 0; ms < 2; ++ms)
        #pragma unroll
        for (int fh = 0; fh < 2; ++fh) {
            const int ri = ms * 2 + fh;
            #pragma unroll
            for (int ns = 0; ns < 2; ++ns)
                #pragma unroll
                for (int cp = 0; cp < 2; ++cp) {
                    const int f = fh * 2 + cp;
                    const int jgl = cbase + ns * 8 + cp;
                    float d0 = acc[0][ms][ns][f];
                    float d1 = acc[1][ms][ns][f];
                    float d2 = acc[2][ms][ns][f];
                    float d3 = acc[3][ms][ns][f];
                    // monotone-uint argmax packing (d+2 > 0)
                    unsigned v0 = (__float_as_uint(d0 + 2.0f) & ~3u) | 0u;
                    unsigned v1 = (__float_as_uint(d1 + 2.0f) & ~3u) | 1u;
                    unsigned v2 = (__float_as_uint(d2 + 2.0f) & ~3u) | 2u;
                    unsigned v3 = (__float_as_uint(d3 + 2.0f) & ~3u) | 3u;
                    unsigned vm = max(max(v0, v1), max(v2, v3));
                    float e0 = fexp2(fmaf(d0, K2C, -K2C));
                    float e1 = fexp2(fmaf(d1, K2C, -K2C));
                    float e2 = fexp2(fmaf(d2, K2C, -K2C));
                    float e3 = fexp2(fmaf(d3, K2C, -K2C));
                    bool nd = true;
                    if (DIAG) nd = (jgl != ig[ri]);
                    if (!DIAG || nd) {
                        s[ri][0] += e0; s[ri][1] += e1;
                        s[ri][2] += e2; s[ri][3] += e3;
                    }
                    bool p = ((ibit[ri] & jb[ns][cp]) != 0u);
                    if (DIAG) p = p && nd;
                    if (p) {
                        Aap[ri] += __uint_as_float(vm & ~3u);   // = best + 2 (2 lsb trunc)
                        unsigned inc = 1u << ((vm & 1u) << 4);
                        if ((vm & 2u) == 0u) Clo[ri] += inc; else Chi[ri] += inc;
                    }
                }
        }
}

// ---------------------------------------------------------------------------
// Main: fp16 mma.sync GEMM + fused epilogue. occupancy 2.
// Grid (4 j-chunks, 64 i-tiles) = 256 CTAs; 256 threads = 8 warps (2i x 4j).
// CTA tile: 64 i x 1024 j x 4 heads, j streamed in 16 tiles of 64.
// SMEM: A 32KB | B0 32KB | B1 32KB | red 2.5KB.
// ---------------------------------------------------------------------------
__global__ __launch_bounds__(256, 2) void k_main() {
    extern __shared__ unsigned char smraw[];
    uint32_t raw  = smem_u32(smraw);
    uint32_t base = (raw + 127) & ~127u;
    unsigned char* sm = smraw + (base - raw);

    const uint32_t Ab  = base;
    const uint32_t B0b = base + 32768;
    const uint32_t B1b = base + 65536;
    float* red = (float*)(sm + 98304);     // 64 rows x 10 floats

    const int tid = threadIdx.x;
    const int lane = tid & 31, wid = tid >> 5;
    const int wi = wid >> 2, wj = wid & 3;          // 2 i-warps x 4 j-warps
    const int by = blockIdx.y, jc = blockIdx.x;
    const int i0 = by * 64;
    const int jbase = jc * 1024;
    const bool has_diag = (jc == (by >> 4));
    const int  jt_d = by & 15;

    prefetch_T(Ab, g_fh + (size_t)i0 * 256, tid);
    prefetch_T(B0b, g_fh + (size_t)jbase * 256, tid);
    CP_COMMIT();

    // ldmatrix geometry
    const int l7 = lane & 7;
    const int khA = (lane >> 4) & 1;
    const uint32_t aoff0 = (uint32_t)((wi * 32 + (lane & 8) + l7) * 128);
    const uint32_t aoff1 = aoff0 + 2048;
    const int nrow = (((lane >> 4) & 1) << 3) + l7;
    const int khB = (lane >> 3) & 1;
    const uint32_t boff0 = (uint32_t)((wj * 16 + nrow) * 128);

    int ig[4]; unsigned ibit[4];
    #pragma unroll
    for (int ri = 0; ri < 4; ++ri) {
        ig[ri] = i0 + wi * 32 + (ri >> 1) * 16 + (ri & 1) * 8 + (lane >> 2);
        ibit[ri] = __ldg(&g_bits[ig[ri] & (BATCH - 1)]);
    }

    float s[4][4], Aap[4];
    unsigned Clo[4], Chi[4];
    #pragma unroll
    for (int ri = 0; ri < 4; ++ri) {
        Aap[ri] = 0.f; Clo[ri] = 0u; Chi[ri] = 0u;
        #pragma unroll
        for (int h = 0; h < 4; ++h) s[ri][h] = 0.f;
    }

    for (int jt = 0; jt < 16; ++jt) {
        const uint32_t Bb = (jt & 1) ? B1b : B0b;
        const int j0 = jbase + jt * 64;

        CP_WAIT0();
        __syncthreads();
        if (jt + 1 < 16)
            prefetch_T((jt & 1) ? B0b : B1b, g_fh + (size_t)(j0 + 64) * 256, tid);
        CP_COMMIT();

        float acc[4][2][2][4];
        #pragma unroll
        for (int h = 0; h < 4; ++h)
            #pragma unroll
            for (int ms = 0; ms < 2; ++ms)
                #pragma unroll
                for (int ns = 0; ns < 2; ++ns)
                    #pragma unroll
                    for (int f = 0; f < 4; ++f) acc[h][ms][ns][f] = 0.f;

        #pragma unroll
        for (int h = 0; h < 4; ++h) {
            const uint32_t Ah = Ab + h * 8192;
            const uint32_t Bh = Bb + h * 8192;
            #pragma unroll
            for (int ks = 0; ks < 4; ++ks) {
                uint32_t A0[4], A1[4], Bq[4];
                uint32_t swA = (uint32_t)(((ks * 2 + khA) ^ l7) << 4);
                uint32_t swB = (uint32_t)(((ks * 2 + khB) ^ l7) << 4);
                LDM4(A0, Ah + aoff0 + swA);
                LDM4(A1, Ah + aoff1 + swA);
                LDM4(Bq, Bh + boff0 + swB);
                MMA16816(acc[h][0][0], A0, Bq[0], Bq[1]);
                MMA16816(acc[h][0][1], A0, Bq[2], Bq[3]);
                MMA16816(acc[h][1][0], A1, Bq[0], Bq[1]);
                MMA16816(acc[h][1][1], A1, Bq[2], Bq[3]);
            }
        }

        if (has_diag && jt == jt_d)
            epi<true >(acc, j0, wj, lane, ig, ibit, s, Aap, Clo, Chi);
        else
            epi<false>(acc, j0, wj, lane, ig, ibit, s, Aap, Clo, Chi);
    }

    // ---- lane-group reduce (4 lanes share rows) ----
    #pragma unroll
    for (int off = 1; off <= 2; off <<= 1) {
        #pragma unroll
        for (int ri = 0; ri < 4; ++ri) {
            #pragma unroll
            for (int h = 0; h < 4; ++h)
                s[ri][h] += __shfl_xor_sync(0xffffffffu, s[ri][h], off);
            Aap[ri] += __shfl_xor_sync(0xffffffffu, Aap[ri], off);
            Clo[ri] += __shfl_xor_sync(0xffffffffu, Clo[ri], off);
            Chi[ri] += __shfl_xor_sync(0xffffffffu, Chi[ri], off);
        }
    }

    // ---- cross-warp combine (4 j-warps), sequential phases ----
    __syncthreads();
    #pragma unroll
    for (int ph = 0; ph < 4; ++ph) {
        if (wj == ph && (lane & 3) == 0) {
            #pragma unroll
            for (int ri = 0; ri < 4; ++ri) {
                int row = wi * 32 + (ri >> 1) * 16 + (ri & 1) * 8 + (lane >> 2);
                float* p = &red[row * 10];
                float c0 = (float)(Clo[ri] & 0xFFFFu), c1 = (float)(Clo[ri] >> 16);
                float c2 = (float)(Chi[ri] & 0xFFFFu), c3 = (float)(Chi[ri] >> 16);
                if (ph == 0) {
                    p[0] = s[ri][0]; p[1] = s[ri][1]; p[2] = s[ri][2]; p[3] = s[ri][3];
                    p[4] = Aap[ri];  p[5] = c0; p[6] = c1; p[7] = c2; p[8] = c3;
                } else {
                    p[0] += s[ri][0]; p[1] += s[ri][1]; p[2] += s[ri][2]; p[3] += s[ri][3];
                    p[4] += Aap[ri];  p[5] += c0; p[6] += c1; p[7] += c2; p[8] += c3;
                }
            }
        }
        __syncthreads();
    }
    if (tid < 64) {
        const float* p = &red[tid * 10];
        float dn = p[5] + p[6] + p[7] + p[8];
        float Acorr = p[4] - 2.0f * dn;     // undo +2 packing bias
        float* o = g_part[jc][i0 + tid];
        o[0] = p[0]; o[1] = p[1]; o[2] = p[2]; o[3] = p[3];
        o[4] = Acorr; o[5] = p[5]; o[6] = p[6]; o[7] = p[7]; o[8] = p[8];
        o[9] = dn;
    }
}

// ---------------------------------------------------------------------------
__global__ void k_loss() {
    int i = blockIdx.x * 128 + threadIdx.x;
    float s[4] = {0, 0, 0, 0}, C[4] = {0, 0, 0, 0}, A = 0.f, dnm = 0.f;
    #pragma unroll
    for (int c = 0; c < 4; ++c) {
        const float* p = g_part[c][i];
        #pragma unroll
        for (int h = 0; h < 4; ++h) { s[h] += p[h]; C[h] += p[5 + h]; }
        A += p[4]; dnm += p[9];
    }
    float sub = 0.f;
    #pragma unroll
    for (int h = 0; h < 4; ++h) sub += C[h] * (INV_T + logf(s[h]));
    float loss = -(A * INV_T - sub) / dnm;
    float ok = isfinite(loss) ? 1.f : 0.f;
    float ls = isfinite(loss) ? loss : 0.f;

    __shared__ float bs[128], bc[128];
    int t = threadIdx.x;
    bs[t] = ls; bc[t] = ok;
    __syncthreads();
    for (int st = 64; st > 0; st >>= 1) {
        if (t < st) { bs[t] += bs[t + st]; bc[t] += bc[t + st]; }
        __syncthreads();
    }
    if (t == 0) { g_red[blockIdx.x * 2] = bs[0]; g_red[blockIdx.x * 2 + 1] = bc[0]; }
}

__global__ void k_final(float* __restrict__ out) {
    if (threadIdx.x == 0) {
        float sv = 0.f, cv = 0.f;
        #pragma unroll
        for (int k = 0; k < 32; ++k) { sv += g_red[2 * k]; cv += g_red[2 * k + 1]; }
        out[0] = sv / cv;
    }
}

// ---------------------------------------------------------------------------
extern "C" void kernel_launch(void* const* d_in, const int* in_sizes, int n_in,
                              void* d_out, int out_size) {
    const float* feats  = (const float*)d_in[0];   // (2048, 2, 256) fp32
    const float* labels = (const float*)d_in[1];   // (2048, 10) fp32
    (void)in_sizes; (void)n_in; (void)out_size;

    k_bits<<<8, 256>>>(labels);
    k_norm<<<NROW, 256>>>(feats);

    const int shmem = 98304 + 2560 + 128;   // A+B0+B1 | red | align slack
    cudaFuncSetAttribute(k_main, cudaFuncAttributeMaxDynamicSharedMemorySize, shmem);
    dim3 grid(4, 64);
    k_main<<<grid, 256, shmem>>>();

    k_loss<<<32, 128>>>();
    k_final<<<1, 32>>>((float*)d_out);
}

// round 5
// speedup vs baseline: 4.7391x; 1.0048x over previous
#include <cuda_runtime.h>
#include <cuda_fp16.h>
#include <cstdint>
#include <math.h>

#define NROW 4096
#define BATCH 2048
#define INV_T 14.285714285714286f
#define K2C   20.609929155556625f   /* INV_T * log2(e) */

__device__ __half   g_fh[NROW * 256];     // normalized features, fp16, [i][e]
__device__ unsigned g_bits[BATCH];
__device__ float    g_part[4][NROW][10];  // [0..3]=s[h], [4]=A, [5..8]=C[h], [9]=den
__device__ float    g_red[64];

// ---------------------------------------------------------------------------
__device__ __forceinline__ uint32_t smem_u32(const void* p) {
    uint32_t a;
    asm("{ .reg .u64 t; cvta.to.shared.u64 t, %1; cvt.u32.u64 %0, t; }" : "=r"(a) : "l"(p));
    return a;
}
__device__ __forceinline__ float fexp2(float x) {
    float y; asm("ex2.approx.f32 %0, %1;" : "=f"(y) : "f"(x)); return y;
}

#define CP_ASYNC(dst, src) asm volatile("cp.async.cg.shared.global [%0], [%1], 16;" :: "r"(dst), "l"(src) : "memory")
#define CP_COMMIT()        asm volatile("cp.async.commit_group;" ::: "memory")
#define CP_WAIT0()         asm volatile("cp.async.wait_group 0;" ::: "memory")

#define LDM4(R, addr) asm volatile( \
    "ldmatrix.sync.aligned.m8n8.x4.shared.b16 {%0,%1,%2,%3}, [%4];" \
    : "=r"((R)[0]), "=r"((R)[1]), "=r"((R)[2]), "=r"((R)[3]) : "r"(addr))

#define LDM2(R, addr) asm volatile( \
    "ldmatrix.sync.aligned.m8n8.x2.shared.b16 {%0,%1}, [%2];" \
    : "=r"((R)[0]), "=r"((R)[1]) : "r"(addr))

#define MMA16816(C, A, b0, b1) asm volatile( \
    "mma.sync.aligned.m16n8k16.row.col.f32.f16.f16.f32 " \
    "{%0,%1,%2,%3}, {%4,%5,%6,%7}, {%8,%9}, {%0,%1,%2,%3};" \
    : "+f"((C)[0]), "+f"((C)[1]), "+f"((C)[2]), "+f"((C)[3]) \
    : "r"((A)[0]), "r"((A)[1]), "r"((A)[2]), "r"((A)[3]), "r"(b0), "r"(b1))

// ---------------------------------------------------------------------------
// Normalize per (row, head) + pack label bits (fused). i = v*BATCH + b.
__global__ void k_norm(const float* __restrict__ feats,
                       const float* __restrict__ labels) {
    int i = blockIdx.x, e = threadIdx.x;
    int v = i >> 11, b = i & (BATCH - 1);

    if (i < BATCH && e < 10) {
        bool p = labels[i * 10 + e] > 0.5f;
        unsigned m = __ballot_sync(0x3FFu, p);
        if (e == 0) g_bits[i] = m & 0x3FFu;
    }

    float val = feats[b * 512 + v * 256 + e];
    float sq = val * val;
    #pragma unroll
    for (int off = 16; off > 0; off >>= 1)
        sq += __shfl_xor_sync(0xffffffffu, sq, off);
    __shared__ float ws[8];
    if ((e & 31) == 0) ws[e >> 5] = sq;
    __syncthreads();
    int h = e >> 6;
    float sum = ws[2 * h] + ws[2 * h + 1];
    float r = 1.0f / fmaxf(sqrtf(sum), 1e-12f);
    g_fh[i * 256 + e] = __float2half_rn(val * r);
}

// ---------------------------------------------------------------------------
// Tile loader: ROWS rows x 4 heads x 64 fp16 (head blocks of ROWS*128B,
// 128B rows, 16B-chunk swizzle chunk' = chunk ^ (row & 7)).
// ---------------------------------------------------------------------------
template<int ROWS>
__device__ __forceinline__ void prefetch_T(uint32_t Tb, const __half* gT, int tid) {
    #pragma unroll
    for (int q = 0; q < ROWS / 8; ++q) {
        int idx = q * 256 + tid;
        int r = idx >> 5, cc = idx & 31;
        int h = cc >> 3, c = cc & 7;
        uint32_t dst = Tb + h * (ROWS * 128) + r * 128 + ((c ^ (r & 7)) << 4);
        const void* src = gT + r * 256 + h * 64 + c * 8;
        CP_ASYNC(dst, src);
    }
}

// ---------------------------------------------------------------------------
// Per-tile epilogue. acc[h][ms][f]. DIAG: this j-tile may contain i==j.
// ---------------------------------------------------------------------------
template<bool DIAG>
__device__ __forceinline__ void epi(
    const float (&acc)[4][2][4], int j0, int wj, int lane,
    const int (&ig)[4], const unsigned (&ibit)[4],
    float (&s)[4][4], float (&Aa)[4], float (&dn)[4],
    unsigned (&Clo)[4], unsigned (&Chi)[4])
{
    const int cbase = j0 + wj * 8 + 2 * (lane & 3);
    const uint2 jb2 = __ldg((const uint2*)&g_bits[cbase & (BATCH - 1)]);
    const unsigned jb[2] = {jb2.x, jb2.y};

    #pragma unroll
    for (int ms = 0; ms < 2; ++ms)
        #pragma unroll
        for (int fh = 0; fh < 2; ++fh) {
            const int ri = ms * 2 + fh;
            #pragma unroll
            for (int cp = 0; cp < 2; ++cp) {
                const int f = fh * 2 + cp;
                const float d0 = acc[0][ms][f];
                const float d1 = acc[1][ms][f];
                const float d2 = acc[2][ms][f];
                const float d3 = acc[3][ms][f];
                const float best = fmaxf(fmaxf(d0, d1), fmaxf(d2, d3));
                const float e0 = fexp2(fmaf(d0, K2C, -K2C));
                const float e1 = fexp2(fmaf(d1, K2C, -K2C));
                const float e2 = fexp2(fmaf(d2, K2C, -K2C));
                const float e3 = fexp2(fmaf(d3, K2C, -K2C));
                bool nd = true;
                if (DIAG) nd = ((cbase + cp) != ig[ri]);
                if (!DIAG || nd) {
                    s[ri][0] += e0; s[ri][1] += e1;
                    s[ri][2] += e2; s[ri][3] += e3;
                }
                bool p = ((ibit[ri] & jb[cp]) != 0u);
                if (DIAG) p = p && nd;
                if (p) {
                    Aa[ri] += best;
                    dn[ri] += 1.0f;
                    if (d0 == best) Clo[ri] += 1u;
                    if (d1 == best) Clo[ri] += 0x10000u;
                    if (d2 == best) Chi[ri] += 1u;
                    if (d3 == best) Chi[ri] += 0x10000u;
                }
            }
        }
}

// ---------------------------------------------------------------------------
// Main: fp16 mma.sync GEMM + fused epilogue. occupancy 2, ~96 regs.
// Grid (4 j-chunks, 64 i-tiles) = 256 CTAs; 256 threads = 8 warps (2i x 4j).
// CTA tile: 64 i x 1024 j x 4 heads, j streamed in 32 tiles of 32.
// SMEM: A 32KB | B0 16KB | B1 16KB | red 2.5KB.
// ---------------------------------------------------------------------------
__global__ __launch_bounds__(256, 2) void k_main() {
    extern __shared__ unsigned char smraw[];
    uint32_t raw  = smem_u32(smraw);
    uint32_t base = (raw + 127) & ~127u;
    unsigned char* sm = smraw + (base - raw);

    const uint32_t Ab  = base;
    const uint32_t B0b = base + 32768;
    const uint32_t B1b = base + 49152;
    float* red = (float*)(sm + 65536);     // 64 rows x 10 floats

    const int tid = threadIdx.x;
    const int lane = tid & 31, wid = tid >> 5;
    const int wi = wid >> 2, wj = wid & 3;          // 2 i-warps x 4 j-warps
    const int by = blockIdx.y, jc = blockIdx.x;
    const int i0 = by * 64;
    const int jbase = jc * 1024;
    const bool has_diag = (jc == (by >> 4));
    const int  jt_d0 = (by & 15) * 2;               // diag spans 2 j-tiles of 32

    prefetch_T<64>(Ab, g_fh + (size_t)i0 * 256, tid);
    prefetch_T<32>(B0b, g_fh + (size_t)jbase * 256, tid);
    CP_COMMIT();

    // ldmatrix geometry
    const int l7 = lane & 7;
    const int khA = (lane >> 4) & 1;
    const uint32_t aoff0 = (uint32_t)((wi * 32 + (lane & 8) + l7) * 128);
    const uint32_t aoff1 = aoff0 + 2048;
    const int khB = (lane >> 3) & 1;
    const uint32_t boff = (uint32_t)((wj * 8 + l7) * 128);

    int ig[4]; unsigned ibit[4];
    #pragma unroll
    for (int ri = 0; ri < 4; ++ri) {
        ig[ri] = i0 + wi * 32 + (ri >> 1) * 16 + (ri & 1) * 8 + (lane >> 2);
        ibit[ri] = __ldg(&g_bits[ig[ri] & (BATCH - 1)]);
    }

    float s[4][4], Aa[4], dn[4];
    unsigned Clo[4], Chi[4];
    #pragma unroll
    for (int ri = 0; ri < 4; ++ri) {
        Aa[ri] = 0.f; dn[ri] = 0.f; Clo[ri] = 0u; Chi[ri] = 0u;
        #pragma unroll
        for (int h = 0; h < 4; ++h) s[ri][h] = 0.f;
    }

    for (int jt = 0; jt < 32; ++jt) {
        const uint32_t Bb = (jt & 1) ? B1b : B0b;
        const int j0 = jbase + jt * 32;

        CP_WAIT0();
        __syncthreads();
        if (jt + 1 < 32)
            prefetch_T<32>((jt & 1) ? B0b : B1b, g_fh + (size_t)(j0 + 32) * 256, tid);
        CP_COMMIT();

        float acc[4][2][4];
        #pragma unroll
        for (int h = 0; h < 4; ++h)
            #pragma unroll
            for (int ms = 0; ms < 2; ++ms)
                #pragma unroll
                for (int f = 0; f < 4; ++f) acc[h][ms][f] = 0.f;

        #pragma unroll
        for (int h = 0; h < 4; ++h) {
            const uint32_t Ah = Ab + h * 8192;
            const uint32_t Bh = Bb + h * 4096;
            #pragma unroll
            for (int ks = 0; ks < 4; ++ks) {
                uint32_t A0[4], A1[4], Bq[2];
                uint32_t swA = (uint32_t)(((ks * 2 + khA) ^ l7) << 4);
                uint32_t swB = (uint32_t)(((ks * 2 + khB) ^ l7) << 4);
                LDM4(A0, Ah + aoff0 + swA);
                LDM4(A1, Ah + aoff1 + swA);
                LDM2(Bq, Bh + boff + swB);
                MMA16816(acc[h][0], A0, Bq[0], Bq[1]);
                MMA16816(acc[h][1], A1, Bq[0], Bq[1]);
            }
        }

        if (has_diag && (jt == jt_d0 || jt == jt_d0 + 1))
            epi<true >(acc, j0, wj, lane, ig, ibit, s, Aa, dn, Clo, Chi);
        else
            epi<false>(acc, j0, wj, lane, ig, ibit, s, Aa, dn, Clo, Chi);
    }

    // ---- lane-group reduce (4 lanes share rows) ----
    #pragma unroll
    for (int off = 1; off <= 2; off <<= 1) {
        #pragma unroll
        for (int ri = 0; ri < 4; ++ri) {
            #pragma unroll
            for (int h = 0; h < 4; ++h)
                s[ri][h] += __shfl_xor_sync(0xffffffffu, s[ri][h], off);
            Aa[ri]  += __shfl_xor_sync(0xffffffffu, Aa[ri], off);
            dn[ri]  += __shfl_xor_sync(0xffffffffu, dn[ri], off);
            Clo[ri] += __shfl_xor_sync(0xffffffffu, Clo[ri], off);
            Chi[ri] += __shfl_xor_sync(0xffffffffu, Chi[ri], off);
        }
    }

    // ---- cross-warp combine (4 j-warps), sequential phases ----
    __syncthreads();
    #pragma unroll
    for (int ph = 0; ph < 4; ++ph) {
        if (wj == ph && (lane & 3) == 0) {
            #pragma unroll
            for (int ri = 0; ri < 4; ++ri) {
                int row = wi * 32 + (ri >> 1) * 16 + (ri & 1) * 8 + (lane >> 2);
                float* p = &red[row * 10];
                float c0 = (float)(Clo[ri] & 0xFFFFu), c1 = (float)(Clo[ri] >> 16);
                float c2 = (float)(Chi[ri] & 0xFFFFu), c3 = (float)(Chi[ri] >> 16);
                if (ph == 0) {
                    p[0] = s[ri][0]; p[1] = s[ri][1]; p[2] = s[ri][2]; p[3] = s[ri][3];
                    p[4] = Aa[ri];   p[5] = c0; p[6] = c1; p[7] = c2; p[8] = c3;
                    p[9] = dn[ri];
                } else {
                    p[0] += s[ri][0]; p[1] += s[ri][1]; p[2] += s[ri][2]; p[3] += s[ri][3];
                    p[4] += Aa[ri];   p[5] += c0; p[6] += c1; p[7] += c2; p[8] += c3;
                    p[9] += dn[ri];
                }
            }
        }
        __syncthreads();
    }
    if (tid < 64) {
        const float* p = &red[tid * 10];
        float* o = g_part[jc][i0 + tid];
        #pragma unroll
        for (int q = 0; q < 10; ++q) o[q] = p[q];
    }
}

// ---------------------------------------------------------------------------
__global__ void k_loss() {
    int i = blockIdx.x * 128 + threadIdx.x;
    float s[4] = {0, 0, 0, 0}, C[4] = {0, 0, 0, 0}, A = 0.f, dnm = 0.f;
    #pragma unroll
    for (int c = 0; c < 4; ++c) {
        const float* p = g_part[c][i];
        #pragma unroll
        for (int h = 0; h < 4; ++h) { s[h] += p[h]; C[h] += p[5 + h]; }
        A += p[4]; dnm += p[9];
    }
    float sub = 0.f;
    #pragma unroll
    for (int h = 0; h < 4; ++h) sub += C[h] * (INV_T + __logf(s[h]));
    float loss = -(A * INV_T - sub) / dnm;
    float ok = isfinite(loss) ? 1.f : 0.f;
    float ls = isfinite(loss) ? loss : 0.f;

    __shared__ float bs[128], bc[128];
    int t = threadIdx.x;
    bs[t] = ls; bc[t] = ok;
    __syncthreads();
    for (int st = 64; st > 0; st >>= 1) {
        if (t < st) { bs[t] += bs[t + st]; bc[t] += bc[t + st]; }
        __syncthreads();
    }
    if (t == 0) { g_red[blockIdx.x * 2] = bs[0]; g_red[blockIdx.x * 2 + 1] = bc[0]; }
}

__global__ void k_final(float* __restrict__ out) {
    if (threadIdx.x == 0) {
        float sv = 0.f, cv = 0.f;
        #pragma unroll
        for (int k = 0; k < 32; ++k) { sv += g_red[2 * k]; cv += g_red[2 * k + 1]; }
        out[0] = sv / cv;
    }
}

// ---------------------------------------------------------------------------
extern "C" void kernel_launch(void* const* d_in, const int* in_sizes, int n_in,
                              void* d_out, int out_size) {
    const float* feats  = (const float*)d_in[0];   // (2048, 2, 256) fp32
    const float* labels = (const float*)d_in[1];   // (2048, 10) fp32
    (void)in_sizes; (void)n_in; (void)out_size;

    k_norm<<<NROW, 256>>>(feats, labels);

    const int shmem = 65536 + 2560 + 128;   // A+B0+B1 | red | align slack
    cudaFuncSetAttribute(k_main, cudaFuncAttributeMaxDynamicSharedMemorySize, shmem);
    dim3 grid(4, 64);
    k_main<<<grid, 256, shmem>>>();

    k_loss<<<32, 128>>>();
    k_final<<<1, 32>>>((float*)d_out);
}